// round 3
// baseline (speedup 1.0000x reference)
#include <cuda_runtime.h>

#define NN3 262144
#define NN2 65536
#define NN1 16384

// Scratch (static device globals; no allocation allowed)
__device__ __align__(256) float g_x8 [NN3*16];
__device__ __align__(256) float g_x7p[NN2*16];
__device__ __align__(256) float g_x7 [NN2*32];
__device__ __align__(256) float g_x6p[NN1*32];
__device__ __align__(256) float g_x6 [NN1*64];
__device__ __align__(256) float g_x7d[NN2*32];
__device__ __align__(256) float g_x8d[NN3*16];

// Generic quadconv: out[n,c] = relu( sum_{j,ci} feat[idx(neigh[n,j]), ci] * w[c, j*CIN+ci] + b[c] )
// SHIFT fuses the unpool: idx(n) = n >> SHIFT (with -1 -> zero row).
template<int CIN,int COUT,int TILE,int NT,int SHIFT,bool RELU>
__global__ __launch_bounds__(NT)
void conv_k(const float* __restrict__ feat, const int* __restrict__ neigh,
            const float* __restrict__ w, const float* __restrict__ b,
            float* __restrict__ out)
{
    constexpr int K   = 9*CIN;
    constexpr int VEC = (CIN % 4 == 0) ? 4 : 1;
    // pad col row stride to avoid smem bank conflicts in the compute phase
    constexpr int STRIDE = (VEC == 4) ? (K + 4) : ((K % 2 == 0) ? (K + 1) : K);
    constexpr int TPN   = NT / TILE;          // threads per node
    constexpr int CO_PER = COUT / TPN;        // outputs per thread

    extern __shared__ float sm[];
    float* swt  = sm;                 // [K][COUT] transposed weights
    float* scol = sm + K*COUT;        // [TILE][STRIDE] im2col tile
    __shared__ int sneigh[TILE*9];

    const int tid  = threadIdx.x;
    const int base = blockIdx.x * TILE;

    // transpose weights into smem: swt[k*COUT + c] = w[c*K + k]
    for (int i = tid; i < K*COUT; i += NT) {
        int k = i / COUT, c = i % COUT;
        swt[i] = w[c*K + k];
    }
    // neighbor indices (apply shift / -1 once)
    for (int i = tid; i < TILE*9; i += NT) {
        int n = neigh[(base + i/9)*9 + (i%9)];
        sneigh[i] = (n < 0) ? -1 : (n >> SHIFT);
    }
    __syncthreads();

    // gather im2col tile
    if (VEC == 4) {
        constexpr int KV = K / 4;
        constexpr int CV = CIN / 4;
        const float4* f4 = (const float4*)feat;
        for (int e = tid; e < TILE*KV; e += NT) {
            int t = e / KV, r = e % KV;
            int j = r / CV;
            int n = sneigh[t*9 + j];
            float4 v = (n < 0) ? make_float4(0.f,0.f,0.f,0.f) : f4[n*CV + (r % CV)];
            *(float4*)&scol[t*STRIDE + r*4] = v;
        }
    } else {
        for (int e = tid; e < TILE*K; e += NT) {
            int t = e / K, r = e % K;
            int j = r / CIN, ci = r % CIN;
            int n = sneigh[t*9 + j];
            scol[t*STRIDE + r] = (n < 0) ? 0.f : feat[n*CIN + ci];
        }
    }
    __syncthreads();

    // compute: thread -> (node t, output group c0..c0+CO_PER)
    const int t  = tid / TPN;
    const int c0 = (tid % TPN) * CO_PER;
    float acc[CO_PER];
    #pragma unroll
    for (int c = 0; c < CO_PER; c++) acc[c] = 0.f;

    const float* colrow = &scol[t*STRIDE];
    #pragma unroll 4
    for (int k = 0; k < K; k++) {
        float v = colrow[k];
        #pragma unroll
        for (int c = 0; c < CO_PER; c++)
            acc[c] += v * swt[k*COUT + c0 + c];
    }

    const int node = base + t;
    #pragma unroll
    for (int c = 0; c < CO_PER; c++) {
        float r = acc[c] + __ldg(&b[c0 + c]);
        if (RELU) r = fmaxf(r, 0.f);
        out[node*COUT + c0 + c] = r;
    }
}

// Max-pool over 4 consecutive child rows (keys are dense arange -> parent = i>>2).
// Inputs are post-relu (>= 0), so the -inf/zero fill case never triggers.
template<int C>
__global__ void pool_k(const float* __restrict__ in, float* __restrict__ out, int NP)
{
    int i = blockIdx.x * blockDim.x + threadIdx.x;   // float4 index
    int total = NP * (C/4);
    if (i >= total) return;
    int p = i / (C/4), cq = i % (C/4);
    const float4* in4 = (const float4*)in;
    float4 a = in4[(4*p+0)*(C/4)+cq];
    float4 b = in4[(4*p+1)*(C/4)+cq];
    float4 c = in4[(4*p+2)*(C/4)+cq];
    float4 d = in4[(4*p+3)*(C/4)+cq];
    float4 r;
    r.x = fmaxf(fmaxf(a.x,b.x), fmaxf(c.x,d.x));
    r.y = fmaxf(fmaxf(a.y,b.y), fmaxf(c.y,d.y));
    r.z = fmaxf(fmaxf(a.z,b.z), fmaxf(c.z,d.z));
    r.w = fmaxf(fmaxf(a.w,b.w), fmaxf(c.w,d.w));
    ((float4*)out)[i] = r;
}

// smem sizes (bytes) per layer
static constexpr int SM1 = (9*1*16   + 256*9  ) * 4;   //  9.8 KB
static constexpr int SM2 = (9*16*32  + 64*148 ) * 4;   // 56.3 KB
static constexpr int SM3 = (9*32*64  + 32*292 ) * 4;   // 111 KB
static constexpr int SM4 = (9*64*32  + 32*580 ) * 4;   // 148 KB
static constexpr int SM5 = (9*32*16  + 64*292 ) * 4;   // 93 KB
static constexpr int SM6 = (9*16*1   + 128*148) * 4;   // 76 KB

extern "C" void kernel_launch(void* const* d_in, const int* in_sizes, int n_in,
                              void* d_out, int out_size)
{
    const float* features = (const float*)d_in[0];
    // d_in[1..3] = keys3/keys2/keys1 (dense arange -> unused; parent = i>>2)
    const int* neighs3 = (const int*)d_in[4];
    const int* neighs2 = (const int*)d_in[5];
    const int* neighs1 = (const int*)d_in[6];
    const float* w_enc1 = (const float*)d_in[7];
    const float* b_enc1 = (const float*)d_in[8];
    const float* w_enc2 = (const float*)d_in[9];
    const float* b_enc2 = (const float*)d_in[10];
    const float* w_enc3 = (const float*)d_in[11];
    const float* b_enc3 = (const float*)d_in[12];
    const float* w_dec1 = (const float*)d_in[13];
    const float* b_dec1 = (const float*)d_in[14];
    const float* w_dec2 = (const float*)d_in[15];
    const float* b_dec2 = (const float*)d_in[16];
    const float* w_head = (const float*)d_in[17];
    const float* b_head = (const float*)d_in[18];
    float* out = (float*)d_out;

    float *x8, *x7p, *x7, *x6p, *x6, *x7d, *x8d;
    cudaGetSymbolAddress((void**)&x8,  g_x8);
    cudaGetSymbolAddress((void**)&x7p, g_x7p);
    cudaGetSymbolAddress((void**)&x7,  g_x7);
    cudaGetSymbolAddress((void**)&x6p, g_x6p);
    cudaGetSymbolAddress((void**)&x6,  g_x6);
    cudaGetSymbolAddress((void**)&x7d, g_x7d);
    cudaGetSymbolAddress((void**)&x8d, g_x8d);

    cudaFuncSetAttribute((const void*)conv_k<1,16,256,256,0,true>,  cudaFuncAttributeMaxDynamicSharedMemorySize, SM1);
    cudaFuncSetAttribute((const void*)conv_k<16,32,64,256,0,true>,  cudaFuncAttributeMaxDynamicSharedMemorySize, SM2);
    cudaFuncSetAttribute((const void*)conv_k<32,64,32,256,0,true>,  cudaFuncAttributeMaxDynamicSharedMemorySize, SM3);
    cudaFuncSetAttribute((const void*)conv_k<64,32,32,256,2,true>,  cudaFuncAttributeMaxDynamicSharedMemorySize, SM4);
    cudaFuncSetAttribute((const void*)conv_k<32,16,64,256,2,true>,  cudaFuncAttributeMaxDynamicSharedMemorySize, SM5);
    cudaFuncSetAttribute((const void*)conv_k<16,1,128,128,0,false>, cudaFuncAttributeMaxDynamicSharedMemorySize, SM6);

    // enc1: [N3,1] -> x8 [N3,16]
    conv_k<1,16,256,256,0,true><<<NN3/256, 256, SM1>>>(features, neighs3, w_enc1, b_enc1, x8);
    // pool: x8 -> x7p [N2,16]
    pool_k<16><<<(NN2*4 + 255)/256, 256>>>(x8, x7p, NN2);
    // enc2: x7p -> x7 [N2,32]
    conv_k<16,32,64,256,0,true><<<NN2/64, 256, SM2>>>(x7p, neighs2, w_enc2, b_enc2, x7);
    // pool: x7 -> x6p [N1,32]
    pool_k<32><<<(NN1*8 + 255)/256, 256>>>(x7, x6p, NN1);
    // enc3: x6p -> x6 [N1,64]
    conv_k<32,64,32,256,0,true><<<NN1/32, 256, SM3>>>(x6p, neighs1, w_enc3, b_enc3, x6);
    // dec1 (fused unpool via neigh>>2): x6 -> x7d [N2,32]
    conv_k<64,32,32,256,2,true><<<NN2/32, 256, SM4>>>(x6, neighs2, w_dec1, b_dec1, x7d);
    // dec2 (fused unpool): x7d -> x8d [N3,16]
    conv_k<32,16,64,256,2,true><<<NN3/64, 256, SM5>>>(x7d, neighs3, w_dec2, b_dec2, x8d);
    // head: x8d -> out [N3,1]
    conv_k<16,1,128,128,0,false><<<NN3/128, 128, SM6>>>(x8d, neighs3, w_head, b_head, out);
}

// round 7
// speedup vs baseline: 2.4643x; 2.4643x over previous
#include <cuda_runtime.h>
#include <cstdint>

#define NN3 262144
#define NN2 65536
#define NN1 16384

// Scratch (static device globals; no allocation allowed)
__device__ __align__(256) float g_x8 [NN3*16];
__device__ __align__(256) float g_x7p[NN2*16];
__device__ __align__(256) float g_x7 [NN2*32];
__device__ __align__(256) float g_x6p[NN1*32];
__device__ __align__(256) float g_x6 [NN1*64];
__device__ __align__(256) float g_x7d[NN2*32];
__device__ __align__(256) float g_x8d[NN3*16];

// ---------------- cp.async helpers ----------------
__device__ __forceinline__ void cp_async16(uint32_t dst, const void* src, int srcsize) {
    asm volatile("cp.async.cg.shared.global [%0], [%1], 16, %2;\n"
                 :: "r"(dst), "l"(src), "r"(srcsize) : "memory");
}
__device__ __forceinline__ void cp_commit() {
    asm volatile("cp.async.commit_group;\n" ::: "memory");
}
template<int N>
__device__ __forceinline__ void cp_wait() {
    asm volatile("cp.async.wait_group %0;\n" :: "n"(N) : "memory");
}

// =====================================================================
// Streamed per-neighbor conv GEMM:
//   out[n,c] = relu( sum_j sum_ci feat[(neigh[n,j])>>SHIFT, ci] * w[c, j*CIN+ci] + b[c] )
// Double-buffered cp.async feat tiles; per-j transposed weight slice;
// register micro-tile MT nodes x 4 outputs per thread.
// =====================================================================
template<int CIN,int COUT,int TILE,int NT,int MT,int SHIFT,bool RELU>
__global__ __launch_bounds__(NT)
void conv2_k(const float* __restrict__ feat, const int* __restrict__ neigh,
             const float* __restrict__ w, const float* __restrict__ b,
             float* __restrict__ out)
{
    constexpr int NTC    = 4;                 // outputs per thread (float4)
    constexpr int OUTG   = COUT / NTC;        // out groups
    constexpr int NG     = NT / OUTG;         // node groups
    static_assert(TILE == MT * NG, "tile shape");
    constexpr int KFULL  = 9 * CIN;
    constexpr int STRIDE = CIN + 4;           // col row stride (floats, x4-aligned, conflict-free)
    constexpr int SW     = COUT + 4;          // wT row stride
    constexpr int CV     = CIN / 4;           // float4 per row
    constexpr int GATHER = TILE * CV;         // float4 per feat buffer
    constexpr int GPT    = GATHER / NT;       // gathers per thread
    constexpr int WPT    = (CIN * COUT) / NT; // weight elems per thread
    static_assert(GATHER % NT == 0 && (CIN*COUT) % NT == 0, "div");

    extern __shared__ float sm[];
    float* scol = sm;                           // [2][TILE*STRIDE]
    float* swt  = sm + 2*TILE*STRIDE;           // [2][CIN*SW]
    int*   sneigh = (int*)(swt + 2*CIN*SW);     // [TILE*9]

    const int tid  = threadIdx.x;
    const int base = blockIdx.x * TILE;
    const uint32_t scol_smem = (uint32_t)__cvta_generic_to_shared(scol);

    // neighbor indices (shift applied once)
    for (int i = tid; i < TILE*9; i += NT) {
        int n = neigh[(base + i/9)*9 + (i%9)];
        sneigh[i] = (n < 0) ? -1 : (n >> SHIFT);
    }
    __syncthreads();

    const int g  = tid / OUTG;        // node group
    const int og = tid % OUTG;        // out group
    const int c0 = og * NTC;
    const float4 bv = *(const float4*)&b[c0];

    float wreg[WPT];

    // ---- stage j=0 ----
    {
        #pragma unroll
        for (int i = 0; i < GPT; i++) {
            int e = i*NT + tid;
            int t = e / CV, q = e % CV;
            int n = sneigh[t*9 + 0];
            const float4* src = (n < 0) ? (const float4*)feat
                                        : (const float4*)feat + (size_t)n*CV + q;
            cp_async16(scol_smem + (uint32_t)((t*STRIDE + q*4)*4), src, (n < 0) ? 0 : 16);
        }
        cp_commit();
        #pragma unroll
        for (int i = 0; i < WPT; i++) {
            int e = i*NT + tid;
            int ci = e % CIN, c = e / CIN;
            wreg[i] = w[c*KFULL + 0*CIN + ci];
        }
        #pragma unroll
        for (int i = 0; i < WPT; i++) {
            int e = i*NT + tid;
            int ci = e % CIN, c = e / CIN;
            swt[ci*SW + c] = wreg[i];
        }
    }

    float acc[MT][4];
    #pragma unroll
    for (int m = 0; m < MT; m++) { acc[m][0]=0.f; acc[m][1]=0.f; acc[m][2]=0.f; acc[m][3]=0.f; }

    #pragma unroll 1
    for (int j = 0; j < 9; j++) {
        const int bi = j & 1;

        // prefetch stage j+1 into the other buffers
        if (j < 8) {
            #pragma unroll
            for (int i = 0; i < GPT; i++) {
                int e = i*NT + tid;
                int t = e / CV, q = e % CV;
                int n = sneigh[t*9 + (j+1)];
                const float4* src = (n < 0) ? (const float4*)feat
                                            : (const float4*)feat + (size_t)n*CV + q;
                cp_async16(scol_smem + (uint32_t)((((bi^1)*TILE + t)*STRIDE + q*4)*4),
                           src, (n < 0) ? 0 : 16);
            }
            cp_commit();
            #pragma unroll
            for (int i = 0; i < WPT; i++) {
                int e = i*NT + tid;
                int ci = e % CIN, c = e / CIN;
                wreg[i] = w[c*KFULL + (j+1)*CIN + ci];
            }
            cp_wait<1>();
        } else {
            cp_wait<0>();
        }
        __syncthreads();   // B1: stage-j feat + weights visible to all

        // ---- compute stage j ----
        const float* colb = scol + bi*TILE*STRIDE;
        const float* wb   = swt  + bi*CIN*SW + c0;
        #pragma unroll
        for (int ci4 = 0; ci4 < CV; ci4++) {
            float4 cv[MT];
            #pragma unroll
            for (int m = 0; m < MT; m++)
                cv[m] = *(const float4*)&colb[(m*NG + g)*STRIDE + ci4*4];
            #pragma unroll
            for (int u = 0; u < 4; u++) {
                float4 wv = *(const float4*)&wb[(ci4*4 + u)*SW];
                #pragma unroll
                for (int m = 0; m < MT; m++) {
                    float v = (u==0) ? cv[m].x : (u==1) ? cv[m].y : (u==2) ? cv[m].z : cv[m].w;
                    acc[m][0] = fmaf(v, wv.x, acc[m][0]);
                    acc[m][1] = fmaf(v, wv.y, acc[m][1]);
                    acc[m][2] = fmaf(v, wv.z, acc[m][2]);
                    acc[m][3] = fmaf(v, wv.w, acc[m][3]);
                }
            }
        }

        // stash prefetched weights (other buffer)
        if (j < 8) {
            float* wdst = swt + (bi^1)*CIN*SW;
            #pragma unroll
            for (int i = 0; i < WPT; i++) {
                int e = i*NT + tid;
                int ci = e % CIN, c = e / CIN;
                wdst[ci*SW + c] = wreg[i];
            }
        }
        __syncthreads();   // B2: stage-j buffers free for the j+2 prefetch
    }

    // epilogue
    #pragma unroll
    for (int m = 0; m < MT; m++) {
        int node = base + m*NG + g;
        float4 r;
        r.x = acc[m][0] + bv.x; r.y = acc[m][1] + bv.y;
        r.z = acc[m][2] + bv.z; r.w = acc[m][3] + bv.w;
        if (RELU) {
            r.x = fmaxf(r.x, 0.f); r.y = fmaxf(r.y, 0.f);
            r.z = fmaxf(r.z, 0.f); r.w = fmaxf(r.w, 0.f);
        }
        *(float4*)&out[node*COUT + c0] = r;
    }
}

// =====================================================================
// Old generic conv (kept for enc1 CIN=1 and head COUT=1, tiny layers)
// =====================================================================
template<int CIN,int COUT,int TILE,int NT,int SHIFT,bool RELU>
__global__ __launch_bounds__(NT)
void conv_k(const float* __restrict__ feat, const int* __restrict__ neigh,
            const float* __restrict__ w, const float* __restrict__ b,
            float* __restrict__ out)
{
    constexpr int K   = 9*CIN;
    constexpr int VEC = (CIN % 4 == 0) ? 4 : 1;
    constexpr int STRIDE = (VEC == 4) ? (K + 4) : ((K % 2 == 0) ? (K + 1) : K);
    constexpr int TPN   = NT / TILE;
    constexpr int CO_PER = COUT / TPN;

    extern __shared__ float sm[];
    float* swt  = sm;
    float* scol = sm + K*COUT;
    __shared__ int sneigh[TILE*9];

    const int tid  = threadIdx.x;
    const int base = blockIdx.x * TILE;

    for (int i = tid; i < K*COUT; i += NT) {
        int k = i / COUT, c = i % COUT;
        swt[i] = w[c*K + k];
    }
    for (int i = tid; i < TILE*9; i += NT) {
        int n = neigh[(base + i/9)*9 + (i%9)];
        sneigh[i] = (n < 0) ? -1 : (n >> SHIFT);
    }
    __syncthreads();

    if (VEC == 4) {
        constexpr int KV = K / 4;
        constexpr int CVv = CIN / 4;
        const float4* f4 = (const float4*)feat;
        for (int e = tid; e < TILE*KV; e += NT) {
            int t = e / KV, r = e % KV;
            int j = r / CVv;
            int n = sneigh[t*9 + j];
            float4 v = (n < 0) ? make_float4(0.f,0.f,0.f,0.f) : f4[n*CVv + (r % CVv)];
            *(float4*)&scol[t*STRIDE + r*4] = v;
        }
    } else {
        for (int e = tid; e < TILE*K; e += NT) {
            int t = e / K, r = e % K;
            int j = r / CIN, ci = r % CIN;
            int n = sneigh[t*9 + j];
            scol[t*STRIDE + r] = (n < 0) ? 0.f : feat[n*CIN + ci];
        }
    }
    __syncthreads();

    const int t  = tid / TPN;
    const int c0 = (tid % TPN) * CO_PER;
    float acc[CO_PER];
    #pragma unroll
    for (int c = 0; c < CO_PER; c++) acc[c] = 0.f;

    const float* colrow = &scol[t*STRIDE];
    #pragma unroll 4
    for (int k = 0; k < K; k++) {
        float v = colrow[k];
        #pragma unroll
        for (int c = 0; c < CO_PER; c++)
            acc[c] += v * swt[k*COUT + c0 + c];
    }

    const int node = base + t;
    #pragma unroll
    for (int c = 0; c < CO_PER; c++) {
        float r = acc[c] + __ldg(&b[c0 + c]);
        if (RELU) r = fmaxf(r, 0.f);
        out[node*COUT + c0 + c] = r;
    }
}

// Max-pool over 4 consecutive child rows (dense keys -> parent = i>>2).
template<int C>
__global__ void pool_k(const float* __restrict__ in, float* __restrict__ out, int NP)
{
    int i = blockIdx.x * blockDim.x + threadIdx.x;
    int total = NP * (C/4);
    if (i >= total) return;
    int p = i / (C/4), cq = i % (C/4);
    const float4* in4 = (const float4*)in;
    float4 a = in4[(4*p+0)*(C/4)+cq];
    float4 b = in4[(4*p+1)*(C/4)+cq];
    float4 c = in4[(4*p+2)*(C/4)+cq];
    float4 d = in4[(4*p+3)*(C/4)+cq];
    float4 r;
    r.x = fmaxf(fmaxf(a.x,b.x), fmaxf(c.x,d.x));
    r.y = fmaxf(fmaxf(a.y,b.y), fmaxf(c.y,d.y));
    r.z = fmaxf(fmaxf(a.z,b.z), fmaxf(c.z,d.z));
    r.w = fmaxf(fmaxf(a.w,b.w), fmaxf(c.w,d.w));
    ((float4*)out)[i] = r;
}

// smem sizes
template<int CIN,int COUT,int TILE>
static constexpr int conv2_smem() {
    return (2*TILE*(CIN+4) + 2*CIN*(COUT+4))*4 + TILE*9*4;
}
static constexpr int SM_ENC2 = conv2_smem<16,32,128>();
static constexpr int SM_ENC3 = conv2_smem<32,64,64>();
static constexpr int SM_DEC1 = conv2_smem<64,32,64>();
static constexpr int SM_DEC2 = conv2_smem<32,16,128>();
static constexpr int SM1 = (9*1*16   + 256*9  ) * 4;
static constexpr int SM6 = (9*16*1   + 128*148) * 4;

extern "C" void kernel_launch(void* const* d_in, const int* in_sizes, int n_in,
                              void* d_out, int out_size)
{
    const float* features = (const float*)d_in[0];
    const int* neighs3 = (const int*)d_in[4];
    const int* neighs2 = (const int*)d_in[5];
    const int* neighs1 = (const int*)d_in[6];
    const float* w_enc1 = (const float*)d_in[7];
    const float* b_enc1 = (const float*)d_in[8];
    const float* w_enc2 = (const float*)d_in[9];
    const float* b_enc2 = (const float*)d_in[10];
    const float* w_enc3 = (const float*)d_in[11];
    const float* b_enc3 = (const float*)d_in[12];
    const float* w_dec1 = (const float*)d_in[13];
    const float* b_dec1 = (const float*)d_in[14];
    const float* w_dec2 = (const float*)d_in[15];
    const float* b_dec2 = (const float*)d_in[16];
    const float* w_head = (const float*)d_in[17];
    const float* b_head = (const float*)d_in[18];
    float* out = (float*)d_out;

    float *x8, *x7p, *x7, *x6p, *x6, *x7d, *x8d;
    cudaGetSymbolAddress((void**)&x8,  g_x8);
    cudaGetSymbolAddress((void**)&x7p, g_x7p);
    cudaGetSymbolAddress((void**)&x7,  g_x7);
    cudaGetSymbolAddress((void**)&x6p, g_x6p);
    cudaGetSymbolAddress((void**)&x6,  g_x6);
    cudaGetSymbolAddress((void**)&x7d, g_x7d);
    cudaGetSymbolAddress((void**)&x8d, g_x8d);

    cudaFuncSetAttribute((const void*)conv_k<1,16,256,256,0,true>,    cudaFuncAttributeMaxDynamicSharedMemorySize, SM1);
    cudaFuncSetAttribute((const void*)conv2_k<16,32,128,256,4,0,true>, cudaFuncAttributeMaxDynamicSharedMemorySize, SM_ENC2);
    cudaFuncSetAttribute((const void*)conv2_k<32,64,64,256,4,0,true>,  cudaFuncAttributeMaxDynamicSharedMemorySize, SM_ENC3);
    cudaFuncSetAttribute((const void*)conv2_k<64,32,64,256,2,2,true>,  cudaFuncAttributeMaxDynamicSharedMemorySize, SM_DEC1);
    cudaFuncSetAttribute((const void*)conv2_k<32,16,128,256,2,2,true>, cudaFuncAttributeMaxDynamicSharedMemorySize, SM_DEC2);
    cudaFuncSetAttribute((const void*)conv_k<16,1,128,128,0,false>,    cudaFuncAttributeMaxDynamicSharedMemorySize, SM6);

    // enc1: [N3,1] -> x8 [N3,16]
    conv_k<1,16,256,256,0,true><<<NN3/256, 256, SM1>>>(features, neighs3, w_enc1, b_enc1, x8);
    // pool: x8 -> x7p [N2,16]
    pool_k<16><<<(NN2*4 + 255)/256, 256>>>(x8, x7p, NN2);
    // enc2: x7p -> x7 [N2,32]
    conv2_k<16,32,128,256,4,0,true><<<NN2/128, 256, SM_ENC2>>>(x7p, neighs2, w_enc2, b_enc2, x7);
    // pool: x7 -> x6p [N1,32]
    pool_k<32><<<(NN1*8 + 255)/256, 256>>>(x7, x6p, NN1);
    // enc3: x6p -> x6 [N1,64]
    conv2_k<32,64,64,256,4,0,true><<<NN1/64, 256, SM_ENC3>>>(x6p, neighs1, w_enc3, b_enc3, x6);
    // dec1 (fused unpool via neigh>>2): x6 -> x7d [N2,32]
    conv2_k<64,32,64,256,2,2,true><<<NN2/64, 256, SM_DEC1>>>(x6, neighs2, w_dec1, b_dec1, x7d);
    // dec2 (fused unpool): x7d -> x8d [N3,16]
    conv2_k<32,16,128,256,2,2,true><<<NN3/128, 256, SM_DEC2>>>(x7d, neighs3, w_dec2, b_dec2, x8d);
    // head: x8d -> out [N3,1]
    conv_k<16,1,128,128,0,false><<<NN3/128, 128, SM6>>>(x8d, neighs3, w_head, b_head, out);
}